// round 3
// baseline (speedup 1.0000x reference)
#include <cuda_runtime.h>
#include <stdint.h>

// Hash constants: ((c+1) * PIS[c]) for c = 0..7 (exact 64-bit products).
// tidx = (idx ^ PP[c]) & (TABLE_SIZE-1); valid since idx >= 0, TABLE_SIZE = 2^19.
__constant__ unsigned long long c_pp[8] = {
    774363409ull, 5308871522ull, 2416379583ull, 400000028ull,
    1671816955ull, 8006180478ull, 5140543849ull, 17074907144ull
};

#define TABLE_MASK 0x7FFFFull
#define NRED 32

static __device__ int g_partial[NRED];

#define PACK2(d, lo, hi) \
    asm("mov.b64 %0, {%1, %2};" : "=l"(d) : "f"(lo), "f"(hi))
#define UNPACK2(lo, hi, d) \
    asm("mov.b64 {%0, %1}, %2;" : "=f"(lo), "=f"(hi) : "l"(d))
#define FMA2(d, a, b, c) \
    asm("fma.rn.f32x2 %0, %1, %2, %3;" : "=l"(d) : "l"(a), "l"(b), "l"(c))

// ---------------------------------------------------------------------------
// Kernel 1: per-block max over depth -> g_partial[blockIdx]
// ---------------------------------------------------------------------------
__global__ void depth_reduce_kernel(const int* __restrict__ depth, int n) {
    int m = 0;
    for (int i = blockIdx.x * blockDim.x + threadIdx.x; i < n;
         i += gridDim.x * blockDim.x)
        m = max(m, depth[i]);
    #pragma unroll
    for (int s = 16; s > 0; s >>= 1)
        m = max(m, __shfl_xor_sync(0xffffffffu, m, s));
    __shared__ int sm[32];
    int w = threadIdx.x >> 5;
    if ((threadIdx.x & 31) == 0) sm[w] = m;
    __syncthreads();
    if (threadIdx.x == 0) {
        int nw = (blockDim.x + 31) >> 5;
        int mm = sm[0];
        for (int i = 1; i < nw; i++) mm = max(mm, sm[i]);
        g_partial[blockIdx.x] = mm;
    }
}

// ---------------------------------------------------------------------------
// Kernel 2: main encoding.
// Block = 256 threads = 2 rays. Warp w: ray_local = w>>2, level pair = w&3
// (levels 2*(w&3), 2*(w&3)+1). Lanes 0-15 -> level A, 16-31 -> level B.
// Within a half-warp: dsub = hl&3 (float4 dim group), p_base = hl>>2; the
// lane produces output for points {p_base, p_base+4, p_base+8, p_base+12},
// amortizing the 8 corner-feature registers over 4 points.
// ---------------------------------------------------------------------------
__global__ void __launch_bounds__(256) nbvh_main_kernel(
    const float* __restrict__ inp,          // [R,16,3]
    const int*   __restrict__ history,      // [R,64]
    const float* __restrict__ nodes_min,    // [N,3]
    const float* __restrict__ nodes_extent, // [N,3]
    const float* __restrict__ emb,          // [524288,16]
    float* __restrict__ out,                // [R, 8*16*16]
    int R)
{
    // padded stride 36 float4 per (warp,half): 576B -> conflict-free feat LDS
    __shared__ float4 s_feat[8][2][36];
    __shared__ float  s_inp[96];            // 2 rays x 48 coords
    __shared__ int    s_activeL;

    const int tid  = threadIdx.x;
    const int w    = tid >> 5;
    const int lane = tid & 31;
    const int rl   = w >> 2;                // ray_local 0/1
    const int half = lane >> 4;             // level within pair
    const int hl   = lane & 15;
    const int dsub = hl & 3;
    const int p_base = hl >> 2;
    const int lvl  = ((w & 3) << 1) + half; // level 0..7
    const int ray  = blockIdx.x * 2 + rl;
    const int rayc = (ray < R) ? ray : (R - 1);

    if (tid == 0) {
        int m = 0;
        #pragma unroll
        for (int i = 0; i < NRED; i++) m = max(m, g_partial[i]);
        s_activeL = (m < 8) ? m : 8;
    }

    // Stage inp coords for both rays (96 floats = 24 float4)
    if (tid < 24) {
        long long base = (long long)blockIdx.x * 96 + tid * 4;
        float4 v = make_float4(0.f, 0.f, 0.f, 0.f);
        if (base + 3 < (long long)R * 48)
            v = reinterpret_cast<const float4*>(inp)[blockIdx.x * 24 + tid];
        reinterpret_cast<float4*>(s_inp)[tid] = v;
    }

    const int idx = history[rayc * 64 + lvl];

    // Gather 8 corner rows (64 float4 per warp = 2 levels x 8 corners x 4)
    {
        const int sub = lane & 3;
        const int cb  = (lane >> 2) & 3;
        #pragma unroll
        for (int j = 0; j < 2; j++) {
            const int c = cb + 4 * j;
            unsigned tix = (unsigned)(((unsigned long long)(unsigned)idx ^
                                       c_pp[c]) & TABLE_MASK);
            s_feat[w][half][c * 4 + sub] =
                reinterpret_cast<const float4*>(emb)[(size_t)tix * 4 + sub];
        }
    }

    // Node box for this lane's level (broadcast within half-warp)
    const float pmx = nodes_min[(size_t)idx * 3 + 0];
    const float pmy = nodes_min[(size_t)idx * 3 + 1];
    const float pmz = nodes_min[(size_t)idx * 3 + 2];
    const float rex = __fdividef(1.0f, nodes_extent[(size_t)idx * 3 + 0]);
    const float rey = __fdividef(1.0f, nodes_extent[(size_t)idx * 3 + 1]);
    const float rez = __fdividef(1.0f, nodes_extent[(size_t)idx * 3 + 2]);

    __syncthreads();

    const float act = (lvl < s_activeL) ? 1.0f : 0.0f;

    // Preload this lane's 8 corner float4s into packed f32x2 registers
    unsigned long long f01[8], f23[8];
    #pragma unroll
    for (int c = 0; c < 8; c++) {
        const float4 f = s_feat[w][half][c * 4 + dsub];
        PACK2(f01[c], f.x, f.y);
        PACK2(f23[c], f.z, f.w);
    }

    const float* ci = s_inp + rl * 48;
    float4* o4 = reinterpret_cast<float4*>(out) + ((size_t)rayc * 8 + lvl) * 64;

    #pragma unroll
    for (int k = 0; k < 4; k++) {
        const int p = p_base + 4 * k;
        float x = fminf(fmaxf((ci[p * 3 + 0] - pmx) * rex, 0.0f), 1.0f);
        float y = fminf(fmaxf((ci[p * 3 + 1] - pmy) * rey, 0.0f), 1.0f);
        float z = fminf(fmaxf((ci[p * 3 + 2] - pmz) * rez, 0.0f), 1.0f);
        const float ix = 1.0f - x, iy = 1.0f - y;
        const float z_a  = (1.0f - z) * act;   // fold act into z terms
        const float za   = z * act;
        const float xy   = x * y,  ixy  = ix * y;
        const float xiy  = x * iy, ixiy = ix * iy;

        float wt[8];
        wt[0] = ixiy * z_a;  wt[1] = xiy * z_a;
        wt[2] = ixy  * z_a;  wt[3] = ixiy * za;
        wt[4] = xiy  * za;   wt[5] = ixy  * za;
        wt[6] = xy   * z_a;  wt[7] = xy   * za;

        unsigned long long a01 = 0ull, a23 = 0ull;
        #pragma unroll
        for (int c = 0; c < 8; c++) {
            unsigned long long ww;
            PACK2(ww, wt[c], wt[c]);
            FMA2(a01, f01[c], ww, a01);
            FMA2(a23, f23[c], ww, a23);
        }

        float4 res;
        UNPACK2(res.x, res.y, a01);
        UNPACK2(res.z, res.w, a23);
        if (ray < R)
            o4[16 * k + hl] = res;   // lanes 0-15 / 16-31: two 256B segments
    }
}

// ---------------------------------------------------------------------------
extern "C" void kernel_launch(void* const* d_in, const int* in_sizes, int n_in,
                              void* d_out, int out_size) {
    const float* inp     = (const float*)d_in[0];
    const int*   history = (const int*)d_in[1];
    const int*   depth   = (const int*)d_in[2];
    const float* nmin    = (const float*)d_in[3];
    const float* next    = (const float*)d_in[4];
    const float* emb     = (const float*)d_in[5];
    float*       out     = (float*)d_out;

    const int R = in_sizes[2];

    depth_reduce_kernel<<<NRED, 256>>>(depth, R);
    nbvh_main_kernel<<<(R + 1) / 2, 256>>>(inp, history, nmin, next, emb, out, R);
}